// round 5
// baseline (speedup 1.0000x reference)
#include <cuda_runtime.h>
#include <cstdint>

// CoordsToNRF: out[b, p] = atoms_flat[p] * (AU2KCALMOLA / MAX_NRF) / ||c_i - c_j||^2
// p = i*(i-1)/2 + j over the strict lower triangle of 128 atoms.
// B = 2048, NC2 = 8128.
//
// Round-5: register-cj + broadcast-ci with full occupancy.
// Per batch, the 316 triangle rows (tile t has 127-32t rows) are flattened
// and split into 4 contiguous 79-row chunks, one per warp. Block = 8 warps
// x 2 batches -> grid 1024, 8192 warps (~55/SM).

#define N_ATOMS 128
#define NC2     8128
#define BLOCK_THREADS 256      // 8 warps
#define BPB 2                  // batches per block
#define ROWS_PER_BATCH 316     // 127 + 95 + 63 + 31
#define CHUNK 79               // rows per warp (316 / 4)

__device__ __forceinline__ float nrf_scale() {
    return (float)(627.5095 * 0.529177 / 100.0);
}

__global__ __launch_bounds__(BLOCK_THREADS)
void coords_to_nrf_kernel(const float* __restrict__ coords,
                          const float* __restrict__ atoms_flat,
                          float* __restrict__ out) {
    __shared__ float4 sc[BPB][N_ATOMS];   // 2 batches, float4-padded: 4KB

    const int warp = threadIdx.x >> 5;    // 0..7
    const int lane = threadIdx.x & 31;
    const int bg   = blockIdx.x;

    // ---- Stage 2 batches' coords (gmem [b][atom][3] -> float4 smem) ----
    const float* cb = coords + (size_t)bg * BPB * (N_ATOMS * 3);
    float* scf = reinterpret_cast<float*>(sc);
    #pragma unroll
    for (int idx = threadIdx.x; idx < BPB * N_ATOMS * 3; idx += BLOCK_THREADS) {
        const int ba  = idx / 3;
        const int dim = idx - ba * 3;
        scf[ba * 4 + dim] = cb[idx];
    }
    __syncthreads();

    const float scale = nrf_scale();

    // Flat-row starts per tile: tile t covers rows [START[t], START[t+1]).
    const int START0 = 0, START1 = 127, START2 = 222, START3 = 285, START4 = 316;
    const int starts[5] = {START0, START1, START2, START3, START4};

    const int bat = warp >> 2;            // batch slot (0 or 1)
    const int wk  = warp & 3;             // chunk index within batch
    const int r0  = wk * CHUNK;
    const int r1  = r0 + CHUNK;           // 316 = 4*79 exactly

    float* ob = out + ((size_t)bg * BPB + bat) * NC2;

    #pragma unroll
    for (int seg = 0; seg < 4; seg++) {
        const int a = (r0 > starts[seg])     ? r0 : starts[seg];
        const int b = (r1 < starts[seg + 1]) ? r1 : starts[seg + 1];
        if (a >= b) continue;

        const int j0 = seg * 32;
        const int j  = j0 + lane;
        const float4 cj = sc[bat][j];     // registers for this segment

        const int i0 = j0 + 1 + (a - starts[seg]);
        int pbase = (i0 * (i0 - 1)) >> 1;
        const int iend = i0 + (b - a);

        #pragma unroll 4
        for (int i = i0; i < iend; i++) {
            const float4 ci = sc[bat][i];          // uniform addr -> broadcast
            const float dx = ci.x - cj.x;
            const float dy = ci.y - cj.y;
            const float dz = ci.z - cj.z;
            const float d2 = fmaf(dx, dx, fmaf(dy, dy, dz * dz));
            if (j < i) {                           // predicated STG
                const int p = pbase + j;
                ob[p] = __fdividef(__ldg(&atoms_flat[p]) * scale, d2);
            }
            pbase += i;
        }
    }
}

extern "C" void kernel_launch(void* const* d_in, const int* in_sizes, int n_in,
                              void* d_out, int out_size) {
    const float* coords     = (const float*)d_in[0];  // [2048, 128, 3] f32
    const float* atoms_flat = (const float*)d_in[1];  // [8128] f32
    float* out = (float*)d_out;                       // [2048, 8128] f32

    const int batch = in_sizes[0] / (N_ATOMS * 3);    // 2048
    coords_to_nrf_kernel<<<batch / BPB, BLOCK_THREADS>>>(coords, atoms_flat, out);
}

// round 6
// speedup vs baseline: 1.0767x; 1.0767x over previous
#include <cuda_runtime.h>
#include <cstdint>

// CoordsToNRF: out[b, p] = atoms_flat[p] * (AU2KCALMOLA / MAX_NRF) / ||c_i - c_j||^2
// p = i*(i-1)/2 + j over the strict lower triangle of 128 atoms.
// B = 2048, NC2 = 8128.
//
// Round-6: packed f32x2 over a batch pair. Each warp-row iteration produces
// 64 outputs (32 lanes x 2 batches) using packed add/mul/fma.rn.f32x2.
// Coords staged per atom as {x0,x1}{y0,y1}{z0,z1} (32B records); cj pair in
// (negated) registers; ci pair = LDS.128 + LDS.64 broadcast; atoms_flat LDG
// shared by both batches; second batch's store folded into a +NC2 offset.

#define N_ATOMS 128
#define NC2     8128
#define BLOCK_THREADS 256      // 8 warps, one batch PAIR per block
#define ROWS_TOTAL 316         // 127 + 95 + 63 + 31 rows per batch(-pair)

typedef unsigned long long u64;

__device__ __forceinline__ u64 f2_add(u64 a, u64 b) {
    u64 r; asm("add.rn.f32x2 %0, %1, %2;" : "=l"(r) : "l"(a), "l"(b)); return r;
}
__device__ __forceinline__ u64 f2_mul(u64 a, u64 b) {
    u64 r; asm("mul.rn.f32x2 %0, %1, %2;" : "=l"(r) : "l"(a), "l"(b)); return r;
}
__device__ __forceinline__ u64 f2_fma(u64 a, u64 b, u64 c) {
    u64 r; asm("fma.rn.f32x2 %0, %1, %2, %3;" : "=l"(r) : "l"(a), "l"(b), "l"(c)); return r;
}
__device__ __forceinline__ u64 f2_pack(float lo, float hi) {
    u64 r; asm("mov.b64 %0, {%1, %2};" : "=l"(r) : "f"(lo), "f"(hi)); return r;
}
__device__ __forceinline__ void f2_unpack(u64 v, float& lo, float& hi) {
    asm("mov.b64 {%0, %1}, %2;" : "=f"(lo), "=f"(hi) : "l"(v));
}

__device__ __forceinline__ float nrf_scale() {
    return (float)(627.5095 * 0.529177 / 100.0);
}

__global__ __launch_bounds__(BLOCK_THREADS, 6)
void coords_to_nrf_kernel(const float* __restrict__ coords,
                          const float* __restrict__ atoms_flat,
                          float* __restrict__ out) {
    // Packed pair coords: atom a -> 8 floats {x0,x1,y0,y1,z0,z1,pad,pad}: 4KB.
    __shared__ float sc[N_ATOMS * 8];

    const int warp = threadIdx.x >> 5;    // 0..7 -> row chunk
    const int lane = threadIdx.x & 31;
    const int bg   = blockIdx.x;          // batch pair index

    // ---- Stage batch pair (gmem [b][atom][3] -> packed-pair smem) ----
    const float* cb = coords + (size_t)bg * 2 * (N_ATOMS * 3);
    #pragma unroll
    for (int idx = threadIdx.x; idx < 2 * N_ATOMS * 3; idx += BLOCK_THREADS) {
        const int q   = idx / (N_ATOMS * 3);       // batch in pair
        const int rem = idx - q * (N_ATOMS * 3);
        const int a   = rem / 3;
        const int d   = rem - a * 3;
        sc[a * 8 + d * 2 + q] = cb[idx];
    }
    __syncthreads();

    const float scale = nrf_scale();

    // Flat rows [0,316) split: 40,40,40,40,39,39,39,39.
    const int over = (warp > 4) ? (warp - 4) : 0;
    const int r0 = 40 * warp - over;
    const int r1 = r0 + ((warp < 4) ? 40 : 39);

    const int starts[5] = {0, 127, 222, 285, 316};

    float* ob = out + (size_t)bg * 2 * NC2;        // batch q=0 plane

    #pragma unroll
    for (int seg = 0; seg < 4; seg++) {
        const int a = (r0 > starts[seg])     ? r0 : starts[seg];
        const int b = (r1 < starts[seg + 1]) ? r1 : starts[seg + 1];
        if (a >= b) continue;

        const int j0 = seg * 32;
        const int j  = j0 + lane;

        // Negated cj pair in registers: sub == add(ci, -cj).
        const float* cjp = &sc[j * 8];
        const u64 ncjx = f2_pack(-cjp[0], -cjp[1]);
        const u64 ncjy = f2_pack(-cjp[2], -cjp[3]);
        const u64 ncjz = f2_pack(-cjp[4], -cjp[5]);

        const int i0 = j0 + 1 + (a - starts[seg]);
        int pbase = (i0 * (i0 - 1)) >> 1;
        const int iend = i0 + (b - a);

        #pragma unroll 2
        for (int i = i0; i < iend; i++) {
            // ci pair: LDS.128 (x0,x1,y0,y1) + LDS.64 (z0,z1), uniform addr.
            const float4 cixy = *reinterpret_cast<const float4*>(&sc[i * 8]);
            const float2 ciz  = *reinterpret_cast<const float2*>(&sc[i * 8 + 4]);

            const u64 dx2 = f2_add(f2_pack(cixy.x, cixy.y), ncjx);
            const u64 dy2 = f2_add(f2_pack(cixy.z, cixy.w), ncjy);
            const u64 dz2 = f2_add(f2_pack(ciz.x,  ciz.y),  ncjz);
            const u64 d2p = f2_fma(dz2, dz2, f2_fma(dy2, dy2, f2_mul(dx2, dx2)));

            if (j < i) {
                float d2a, d2b;
                f2_unpack(d2p, d2a, d2b);
                const int p = pbase + j;
                const float aval = __ldg(&atoms_flat[p]) * scale;
                float* o = ob + p;
                o[0]   = __fdividef(aval, d2a);    // MUFU.RCP + FMUL
                o[NC2] = __fdividef(aval, d2b);    // same base reg, +imm offset
            }
            pbase += i;
        }
    }
}

extern "C" void kernel_launch(void* const* d_in, const int* in_sizes, int n_in,
                              void* d_out, int out_size) {
    const float* coords     = (const float*)d_in[0];  // [2048, 128, 3] f32
    const float* atoms_flat = (const float*)d_in[1];  // [8128] f32
    float* out = (float*)d_out;                       // [2048, 8128] f32

    const int batch = in_sizes[0] / (N_ATOMS * 3);    // 2048
    coords_to_nrf_kernel<<<batch / 2, BLOCK_THREADS>>>(coords, atoms_flat, out);
}

// round 7
// speedup vs baseline: 1.3232x; 1.2290x over previous
#include <cuda_runtime.h>
#include <cstdint>

// CoordsToNRF: out[b, p] = atoms_flat[p] * (AU2KCALMOLA / MAX_NRF) / ||c_i - c_j||^2
// p = i*(i-1)/2 + j over the strict lower triangle of 128 atoms.
// B = 2048, NC2 = 8128.
//
// Round-7: packed f32x2 batch pair (R6) with:
//  - branch-free inner loop: unconditional compute, clamped atoms LDG,
//    predicated @P STG pair only (no BSSY/BSYNC per row)
//  - single-wave grid: launch_bounds(256,7) -> all 1024 blocks resident
//  - unroll 4 for LDS MLP

#define N_ATOMS 128
#define NC2     8128
#define BLOCK_THREADS 256      // 8 warps, one batch PAIR per block

typedef unsigned long long u64;

__device__ __forceinline__ u64 f2_add(u64 a, u64 b) {
    u64 r; asm("add.rn.f32x2 %0, %1, %2;" : "=l"(r) : "l"(a), "l"(b)); return r;
}
__device__ __forceinline__ u64 f2_mul(u64 a, u64 b) {
    u64 r; asm("mul.rn.f32x2 %0, %1, %2;" : "=l"(r) : "l"(a), "l"(b)); return r;
}
__device__ __forceinline__ u64 f2_fma(u64 a, u64 b, u64 c) {
    u64 r; asm("fma.rn.f32x2 %0, %1, %2, %3;" : "=l"(r) : "l"(a), "l"(b), "l"(c)); return r;
}
__device__ __forceinline__ u64 f2_pack(float lo, float hi) {
    u64 r; asm("mov.b64 %0, {%1, %2};" : "=l"(r) : "f"(lo), "f"(hi)); return r;
}
__device__ __forceinline__ void f2_unpack(u64 v, float& lo, float& hi) {
    asm("mov.b64 {%0, %1}, %2;" : "=f"(lo), "=f"(hi) : "l"(v));
}

__device__ __forceinline__ float nrf_scale() {
    return (float)(627.5095 * 0.529177 / 100.0);
}

__global__ __launch_bounds__(BLOCK_THREADS, 7)
void coords_to_nrf_kernel(const float* __restrict__ coords,
                          const float* __restrict__ atoms_flat,
                          float* __restrict__ out) {
    // Packed pair coords: atom a -> {x0,x1,y0,y1,z0,z1,pad,pad}: 4KB.
    __shared__ float sc[N_ATOMS * 8];

    const int warp = threadIdx.x >> 5;    // 0..7 -> row chunk
    const int lane = threadIdx.x & 31;
    const int bg   = blockIdx.x;          // batch pair index

    // ---- Stage batch pair (gmem [b][atom][3] -> packed-pair smem) ----
    const float* cb = coords + (size_t)bg * 2 * (N_ATOMS * 3);
    #pragma unroll
    for (int idx = threadIdx.x; idx < 2 * N_ATOMS * 3; idx += BLOCK_THREADS) {
        const int q   = idx / (N_ATOMS * 3);       // batch in pair
        const int rem = idx - q * (N_ATOMS * 3);
        const int a   = rem / 3;
        const int d   = rem - a * 3;
        sc[a * 8 + d * 2 + q] = cb[idx];
    }
    __syncthreads();

    const float scale = nrf_scale();

    // Flat rows [0,316) split: 40,40,40,40,39,39,39,39.
    const int over = (warp > 4) ? (warp - 4) : 0;
    const int r0 = 40 * warp - over;
    const int r1 = r0 + ((warp < 4) ? 40 : 39);

    const int starts[5] = {0, 127, 222, 285, 316};

    float* ob = out + (size_t)bg * 2 * NC2;        // batch q=0 plane

    #pragma unroll
    for (int seg = 0; seg < 4; seg++) {
        const int a = (r0 > starts[seg])     ? r0 : starts[seg];
        const int b = (r1 < starts[seg + 1]) ? r1 : starts[seg + 1];
        if (a >= b) continue;

        const int j0 = seg * 32;
        const int j  = j0 + lane;

        // Negated cj pair in registers: sub == add(ci, -cj).
        const float* cjp = &sc[j * 8];
        const u64 ncjx = f2_pack(-cjp[0], -cjp[1]);
        const u64 ncjy = f2_pack(-cjp[2], -cjp[3]);
        const u64 ncjz = f2_pack(-cjp[4], -cjp[5]);

        const int i0 = j0 + 1 + (a - starts[seg]);
        int pbase = (i0 * (i0 - 1)) >> 1;
        const int iend = i0 + (b - a);

        #pragma unroll 4
        for (int i = i0; i < iend; i++) {
            // ci pair: LDS.128 + LDS.64, uniform address -> broadcast.
            const float4 cixy = *reinterpret_cast<const float4*>(&sc[i * 8]);
            const float2 ciz  = *reinterpret_cast<const float2*>(&sc[i * 8 + 4]);

            const u64 dx2 = f2_add(f2_pack(cixy.x, cixy.y), ncjx);
            const u64 dy2 = f2_add(f2_pack(cixy.z, cixy.w), ncjy);
            const u64 dz2 = f2_add(f2_pack(ciz.x,  ciz.y),  ncjz);
            const u64 d2p = f2_fma(dz2, dz2, f2_fma(dy2, dy2, f2_mul(dx2, dx2)));

            float d2a, d2b;
            f2_unpack(d2p, d2a, d2b);

            const int p  = pbase + j;
            const int pc = (p < NC2 - 1) ? p : (NC2 - 1);   // safe LDG for masked lanes
            const float aval = __ldg(&atoms_flat[pc]) * scale;
            const float ra = __fdividef(aval, d2a);          // MUFU.RCP + FMUL
            const float rb = __fdividef(aval, d2b);

            if (j < i) {                 // bare store pair -> @P STG, no BSSY
                ob[p]       = ra;
                ob[p + NC2] = rb;
            }
            pbase += i;
        }
    }
}

extern "C" void kernel_launch(void* const* d_in, const int* in_sizes, int n_in,
                              void* d_out, int out_size) {
    const float* coords     = (const float*)d_in[0];  // [2048, 128, 3] f32
    const float* atoms_flat = (const float*)d_in[1];  // [8128] f32
    float* out = (float*)d_out;                       // [2048, 8128] f32

    const int batch = in_sizes[0] / (N_ATOMS * 3);    // 2048
    coords_to_nrf_kernel<<<batch / 2, BLOCK_THREADS>>>(coords, atoms_flat, out);
}